// round 17
// baseline (speedup 1.0000x reference)
#include <cuda_runtime.h>
#include <cuda_fp16.h>
#include <math.h>

#define BB   2
#define CC   64
#define NPTS 20000
#define KK   16
#define CO   64
#define NODES (BB * NPTS)

// Scratch (device globals: allocation-free rule)
__device__ uint4 g_U[NODES * 8];      // (W1-W2) @ x + bias   per node, fp16
__device__ uint4 g_V[NODES * 8];      // W2      @ x          per node, fp16
__device__ float g_posT[NODES * 4];   // pos transposed to [node][4]

__device__ __forceinline__ unsigned f2h2(float lo, float hi) {
    __half2 h = __floats2half2_rn(lo, hi);
    return *reinterpret_cast<unsigned*>(&h);
}
__device__ __forceinline__ __half2 u2h(unsigned x) {
    return *reinterpret_cast<__half2*>(&x);
}
__device__ __forceinline__ __half2 hmax2_xor(__half2 a, int m) {
    unsigned o = __shfl_xor_sync(0xFFFFFFFFu, *reinterpret_cast<unsigned*>(&a), m);
    return __hmax2(a, u2h(o));
}

__device__ __forceinline__ void mma_16x8x16(float d[4],
                                            unsigned a0, unsigned a1,
                                            unsigned a2, unsigned a3,
                                            unsigned b0, unsigned b1) {
    asm volatile(
        "mma.sync.aligned.m16n8k16.row.col.f32.f16.f16.f32 "
        "{%0,%1,%2,%3}, {%4,%5,%6,%7}, {%8,%9}, {%0,%1,%2,%3};"
        : "+f"(d[0]), "+f"(d[1]), "+f"(d[2]), "+f"(d[3])
        : "r"(a0), "r"(a1), "r"(a2), "r"(a3), "r"(b0), "r"(b1));
}

// ---------------------------------------------------------------------------
// Kernel 1: per-node transform via tensor-core mma (fp16 in, fp32 acc),
// bias folded into U in fp32. R17: 512-thread blocks — each of 16 warps
// computes a 16-node x 32-output tile (acc 16 regs instead of 32), cutting
// per-thread registers so 2 blocks/SM = 32 warps/SM (was 16). uv was
// latency/sync-bound at low occupancy, not issue- or traffic-bound.
// ---------------------------------------------------------------------------
__global__ __launch_bounds__(512) void uv_kernel(const float* __restrict__ x,
                                                 const float* __restrict__ pos,
                                                 const float* __restrict__ W,
                                                 const float* __restrict__ bias) {
    __shared__ __half sx[64 * 72];    //  9 KB
    __shared__ __half sW[128 * 72];   // 18 KB

    int tid  = threadIdx.x;
    int base = blockIdx.x * 64;

    // --- Stage W (combined + transposed-to-[oc][c], fp16). Coalesced reads.
#pragma unroll
    for (int j = 0; j < 8; ++j) {
        int i = tid + j * 512;
        int o = i >> 6, c = i & 63;
        float w1 = W[o * 128 + c];
        float w2 = W[o * 128 + 64 + c];
        sW[o * 72 + c]        = __float2half(w1 - w2);
        sW[(64 + o) * 72 + c] = __float2half(w2);
    }

    // --- Stage x tile: sx[nl][c] = fp16(x[b, c, n]). Coalesced reads over n.
#pragma unroll
    for (int j = 0; j < 8; ++j) {
        int i  = tid + j * 512;
        int c  = i >> 6, nl = i & 63;
        int node = base + nl;
        int b  = node / NPTS;
        int n  = node - b * NPTS;
        sx[nl * 72 + c] = __float2half(x[b * CC * NPTS + c * NPTS + n]);
    }

    // --- pos transpose by the first 64 threads.
    if (tid < 64) {
        int node = base + tid;
        int b = node / NPTS;
        int n = node - b * NPTS;
        const float* pb = pos + b * 3 * NPTS + n;
        float4 p;
        p.x = pb[0];
        p.y = pb[NPTS];
        p.z = pb[2 * NPTS];
        p.w = 0.0f;
        reinterpret_cast<float4*>(g_posT)[node] = p;
    }
    __syncthreads();

    int warp = tid >> 5;
    int lane = tid & 31;
    int m0   = (warp & 3) * 16;    // m-tile (4 tiles of 16 nodes)
    int hsel = (warp >> 2) & 1;    // 0 -> U, 1 -> V
    int nh   = warp >> 3;          // n-half: n-tiles nh*4 .. nh*4+3
    int g    = lane >> 2;
    int t    = lane & 3;

    float acc[4][4];
#pragma unroll
    for (int j = 0; j < 4; ++j)
#pragma unroll
        for (int r = 0; r < 4; ++r) acc[j][r] = 0.0f;

    const __half* arow0 = sx + (m0 + g) * 72 + 2 * t;
    const __half* arow1 = sx + (m0 + g + 8) * 72 + 2 * t;
    const __half* brow  = sW + (hsel * 64 + g) * 72 + 2 * t;

#pragma unroll
    for (int k = 0; k < 4; ++k) {
        unsigned a0 = *reinterpret_cast<const unsigned*>(arow0 + 16 * k);
        unsigned a1 = *reinterpret_cast<const unsigned*>(arow1 + 16 * k);
        unsigned a2 = *reinterpret_cast<const unsigned*>(arow0 + 16 * k + 8);
        unsigned a3 = *reinterpret_cast<const unsigned*>(arow1 + 16 * k + 8);
#pragma unroll
        for (int j = 0; j < 4; ++j) {
            int nt = nh * 4 + j;
            unsigned b0 = *reinterpret_cast<const unsigned*>(brow + nt * 8 * 72 + 16 * k);
            unsigned b1 = *reinterpret_cast<const unsigned*>(brow + nt * 8 * 72 + 16 * k + 8);
            mma_16x8x16(acc[j], a0, a1, a2, a3, b0, b1);
        }
    }

    // Fold bias into U (fp32, before the fp16 quantization).
    if (hsel == 0) {
        const float2* bias2 = reinterpret_cast<const float2*>(bias);
#pragma unroll
        for (int j = 0; j < 4; ++j) {
            float2 bb = bias2[(nh * 4 + j) * 4 + t];   // output cols 2((nh*4+j)*4+t), +1
            acc[j][0] += bb.x;  acc[j][1] += bb.y;     // row g
            acc[j][2] += bb.x;  acc[j][3] += bb.y;     // row g+8
        }
    }

    // Direct stores (smem-staged epilogue measured neutral in R16).
    unsigned* dstA = reinterpret_cast<unsigned*>(hsel ? g_V : g_U);
    int nlo = base + m0 + g;
#pragma unroll
    for (int j = 0; j < 4; ++j) {
        int col = (nh * 4 + j) * 4 + t;
        dstA[nlo * 32 + col]       = f2h2(acc[j][0], acc[j][1]);
        dstA[(nlo + 8) * 32 + col] = f2h2(acc[j][2], acc[j][3]);
    }
}

// ---------------------------------------------------------------------------
// Kernel 2: per-edge combine + suppression + max over K.
// (byte-identical to R15/R16 — best measured edge at ~21us; reorder/__ldcg/
// barrier-removal all regressed, so this is its floor.)
// ---------------------------------------------------------------------------
__global__ __launch_bounds__(256) void edge_kernel(const int* __restrict__ ei,
                                                   float* __restrict__ out) {
    __shared__ float    sm[8 * 66];   // output staging
    __shared__ unsigned ssh[8 * 16];  // suppression as half2(s,s), per warp/k
    __shared__ int      si[8 * 32];   // [warp][0..15: i1 (center), 16..31: i0]

    int tid  = threadIdx.x;
    int warp = tid >> 5;
    int lane = tid & 31;

    int g = blockIdx.x * 8 + warp;   // 20000 % 8 == 0 -> block never crosses batch
    int b = g / NPTS;
    int n = g - b * NPTS;

    const int* e0 = ei + (b * NPTS + n) * KK;                    // neighbor idx
    const int* e1 = ei + (BB * NPTS * KK) + (b * NPTS + n) * KK; // center idx

    const uint4*  Ub = g_U + b * NPTS * 8;
    const uint4*  Vb = g_V + b * NPTS * 8;
    const float4* Pb = reinterpret_cast<const float4*>(g_posT) + b * NPTS;

    if (lane < KK) {
        int i0 = e0[lane];
        int i1 = e1[lane];
        si[warp * 32 + lane]      = i1;
        si[warp * 32 + 16 + lane] = i0;
        float4 p1 = Pb[i1];
        float4 p0 = Pb[i0];
        float dx = p1.x - p0.x, dy = p1.y - p0.y, dz = p1.z - p0.z;
        float dis = sqrtf(dx * dx + dy * dy + dz * dz);
        float s = 2.0f / (1.0f + __expf(dis));   // 2*sigmoid(-dis)
        ssh[warp * 16 + lane] = f2h2(s, s);
    }
    __syncthreads();   // block-wide phase alignment (load-bearing for L1tex)

    int esub = lane >> 3;    // which of 4 edges this pass
    int q    = lane & 7;     // which 16B quad of the 128B row

    uint4    u[4], v[4];
    unsigned sh[4];
#pragma unroll
    for (int p = 0; p < 4; ++p) {
        int k  = p * 4 + esub;
        int i1 = si[warp * 32 + k];
        int i0 = si[warp * 32 + 16 + k];
        u[p]  = Ub[i1 * 8 + q];
        v[p]  = Vb[i0 * 8 + q];
        sh[p] = ssh[warp * 16 + k];
    }

    const __half2 z = __floats2half2_rn(0.0f, 0.0f);
    __half2 a0 = z, a1 = z, a2 = z, a3 = z;   // relu * positive => >= 0

#pragma unroll
    for (int p = 0; p < 4; ++p) {
        __half2 s2 = u2h(sh[p]);
        a0 = __hmax2(a0, __hmul2(__hmax2(__hadd2(u2h(u[p].x), u2h(v[p].x)), z), s2));
        a1 = __hmax2(a1, __hmul2(__hmax2(__hadd2(u2h(u[p].y), u2h(v[p].y)), z), s2));
        a2 = __hmax2(a2, __hmul2(__hmax2(__hadd2(u2h(u[p].z), u2h(v[p].z)), z), s2));
        a3 = __hmax2(a3, __hmul2(__hmax2(__hadd2(u2h(u[p].w), u2h(v[p].w)), z), s2));
    }

    // Max over esub: lanes {q, q+8, q+16, q+24} hold the 4 edge groups.
    a0 = hmax2_xor(a0, 8);  a1 = hmax2_xor(a1, 8);
    a2 = hmax2_xor(a2, 8);  a3 = hmax2_xor(a3, 8);
    a0 = hmax2_xor(a0, 16); a1 = hmax2_xor(a1, 16);
    a2 = hmax2_xor(a2, 16); a3 = hmax2_xor(a3, 16);

    if (esub == 0) {   // lanes 0..7 write outputs 8q..8q+7 (float)
        float2* dst = reinterpret_cast<float2*>(sm + warp * 66 + q * 8);
        dst[0] = __half22float2(a0);
        dst[1] = __half22float2(a1);
        dst[2] = __half22float2(a2);
        dst[3] = __half22float2(a3);
    }
    __syncthreads();

    int base = blockIdx.x * 8;
    int ob = base / NPTS;               // batch of this block's points
    int on = base - ob * NPTS;          // first point index within batch
#pragma unroll
    for (int e = tid; e < CO * 8; e += 256) {
        int o  = e >> 3;
        int nn = e & 7;
        out[(ob * CO + o) * NPTS + on + nn] = sm[nn * 66 + o];
    }
}

extern "C" void kernel_launch(void* const* d_in, const int* in_sizes, int n_in,
                              void* d_out, int out_size) {
    const float* x    = (const float*)d_in[0];
    const int*   ei   = (const int*)d_in[1];
    const float* pos  = (const float*)d_in[2];
    const float* W    = (const float*)d_in[3];
    const float* bias = (const float*)d_in[4];
    float* out = (float*)d_out;

    uv_kernel<<<NODES / 64, 512>>>(x, pos, W, bias);
    edge_kernel<<<NODES / 8, 256>>>(ei, out);
}